// round 1
// baseline (speedup 1.0000x reference)
#include <cuda_runtime.h>
#include <math.h>

#define BB 2
#define SS 2048
#define EE 1024
#define HH 16
#define DD 64
#define MM (BB*SS)          // 4096 rows for the projection GEMMs

// Scratch (no cudaMalloc allowed)
__device__ float g_Q[BB*HH*SS*DD];
__device__ float g_K[BB*HH*SS*DD];
__device__ float g_V[BB*HH*SS*DD];
__device__ float g_A[BB*SS*EE];

// ---------------------------------------------------------------------------
// SGEMM: out = X @ W^T + bias.  X:[M=4096, K=1024] row-major, W:[N=1024, K=1024]
// row-major (nn.Linear convention).  MODE 0: plain [M,N] output.
// MODE 1: scatter to [B,H,S,D] layout (for Q/K/V).
// 128x128 block tile, BK=8, 256 threads, 8x8 micro-tile per thread.
// ---------------------------------------------------------------------------
template <int MODE>
__global__ __launch_bounds__(256) void sgemm_kernel(
    const float* __restrict__ X, const float* __restrict__ W,
    const float* __restrict__ bias, float* __restrict__ out)
{
    const int K = EE;
    __shared__ float Xs[8][132];
    __shared__ float Ws[8][132];

    int t  = threadIdx.x;
    int tx = t & 15;          // 0..15 -> col groups
    int ty = t >> 4;          // 0..15 -> row groups
    int bm = blockIdx.y * 128;
    int bn = blockIdx.x * 128;

    float acc[8][8];
#pragma unroll
    for (int i = 0; i < 8; i++)
#pragma unroll
        for (int j = 0; j < 8; j++) acc[i][j] = 0.f;

    int lrow = t >> 1;            // 0..127
    int lc4  = (t & 1) * 4;       // 0 or 4
    const float* Xp = X + (bm + lrow) * K + lc4;
    const float* Wp = W + (bn + lrow) * K + lc4;

    for (int k0 = 0; k0 < K; k0 += 8) {
        float4 xa = *(const float4*)(Xp + k0);
        float4 wa = *(const float4*)(Wp + k0);
        Xs[lc4 + 0][lrow] = xa.x; Xs[lc4 + 1][lrow] = xa.y;
        Xs[lc4 + 2][lrow] = xa.z; Xs[lc4 + 3][lrow] = xa.w;
        Ws[lc4 + 0][lrow] = wa.x; Ws[lc4 + 1][lrow] = wa.y;
        Ws[lc4 + 2][lrow] = wa.z; Ws[lc4 + 3][lrow] = wa.w;
        __syncthreads();

#pragma unroll
        for (int kk = 0; kk < 8; kk++) {
            float4 a0 = *(const float4*)&Xs[kk][ty * 4];
            float4 a1 = *(const float4*)&Xs[kk][64 + ty * 4];
            float4 b0 = *(const float4*)&Ws[kk][tx * 4];
            float4 b1 = *(const float4*)&Ws[kk][64 + tx * 4];
            float a[8] = {a0.x, a0.y, a0.z, a0.w, a1.x, a1.y, a1.z, a1.w};
            float b[8] = {b0.x, b0.y, b0.z, b0.w, b1.x, b1.y, b1.z, b1.w};
#pragma unroll
            for (int i = 0; i < 8; i++)
#pragma unroll
                for (int j = 0; j < 8; j++)
                    acc[i][j] = fmaf(a[i], b[j], acc[i][j]);
        }
        __syncthreads();
    }

    // Epilogue: rows = bm + {ty*4+i, 64+ty*4+i}, cols = bn + {tx*4+j, 64+tx*4+j}
#pragma unroll
    for (int ih = 0; ih < 2; ih++) {
#pragma unroll
        for (int i = 0; i < 4; i++) {
            int row = bm + ih * 64 + ty * 4 + i;
#pragma unroll
            for (int jh = 0; jh < 2; jh++) {
                int col = bn + jh * 64 + tx * 4;
                float4 r;
                r.x = acc[ih * 4 + i][jh * 4 + 0] + bias[col + 0];
                r.y = acc[ih * 4 + i][jh * 4 + 1] + bias[col + 1];
                r.z = acc[ih * 4 + i][jh * 4 + 2] + bias[col + 2];
                r.w = acc[ih * 4 + i][jh * 4 + 3] + bias[col + 3];
                if (MODE == 0) {
                    *(float4*)&out[row * EE + col] = r;
                } else {
                    int b_ = row >> 11;         // / SS
                    int s_ = row & (SS - 1);
                    int h_ = col >> 6;          // / DD
                    int d_ = col & (DD - 1);
                    *(float4*)&out[((b_ * HH + h_) * SS + s_) * DD + d_] = r;
                }
            }
        }
    }
}

// ---------------------------------------------------------------------------
// RoPE on Q and K in [B,H,S,D] layout.  One thread per (bh, s, pair i<32).
// ---------------------------------------------------------------------------
__global__ void rope_kernel(float* __restrict__ Q, float* __restrict__ K)
{
    int gid = blockIdx.x * blockDim.x + threadIdx.x;   // BB*HH*SS*32 = 2^21
    int i  = gid & 31;
    int s  = (gid >> 5) & (SS - 1);
    int bh = gid >> 16;                                // 32*2048 = 2^16
    int base = (bh * SS + s) * DD;

    // 10000^{-i/32} = 2^{-i * log2(10000)/32}
    float freq = exp2f(-(float)i * (13.287712379549449f / 32.0f));
    float ang  = (float)s * freq;
    float sn, cs;
    sincosf(ang, &sn, &cs);

    float q0 = Q[base + i], q1 = Q[base + i + 32];
    Q[base + i]      = q0 * cs - q1 * sn;
    Q[base + i + 32] = q1 * cs + q0 * sn;
    float k0 = K[base + i], k1 = K[base + i + 32];
    K[base + i]      = k0 * cs - k1 * sn;
    K[base + i + 32] = k1 * cs + k0 * sn;
}

// ---------------------------------------------------------------------------
// Flash attention (causal), fp32.  One CTA per (bh, 64-row q tile).
// 256 threads: thread t handles row r = t>>2, column/dim chunks selected by
// g = t&3:  owned indices c = c4*4+j  <->  col/dim = c4*16 + g*4 + j.
// This mapping makes all hot LDS.128 accesses conflict-free-ish (4 distinct
// 16B chunks + 8-lane broadcast).
// smem: Qs (stride 68), Ks (stride 68, reused as P), Vs (stride 64).
// ---------------------------------------------------------------------------
#define ATTN_SMEM_BYTES ((64*68*2 + 64*64) * 4)   // 51200

__global__ __launch_bounds__(256) void attn_kernel(
    const float* __restrict__ Q, const float* __restrict__ K,
    const float* __restrict__ V, float* __restrict__ A)
{
    extern __shared__ float sm[];
    float* Qs = sm;                 // 64 * 68
    float* Ks = sm + 64 * 68;       // 64 * 68 (reused for P)
    float* Vs = sm + 2 * 64 * 68;   // 64 * 64

    int t = threadIdx.x;
    int r = t >> 2;                 // 0..63 (query row within tile)
    int g = t & 3;

    int iq = blockIdx.x;            // q tile index
    int bh = blockIdx.y;            // b*H + h
    int hb = bh * SS * DD;          // base into [B,H,S,D]
    int q0row = iq * 64;
    int qrow  = q0row + r;          // global query row (within this b,h)

    // Load Q tile, pre-scaled by 1/sqrt(D) = 0.125
#pragma unroll
    for (int u = 0; u < 4; u++) {
        int idx = t + u * 256;
        int row = idx >> 4;
        int c4  = (idx & 15) * 4;
        float4 v = *(const float4*)&Q[hb + (q0row + row) * DD + c4];
        v.x *= 0.125f; v.y *= 0.125f; v.z *= 0.125f; v.w *= 0.125f;
        *(float4*)&Qs[row * 68 + c4] = v;
    }

    float o[16];
#pragma unroll
    for (int c = 0; c < 16; c++) o[c] = 0.f;
    float m_i = -1e30f, l_i = 0.f;

    for (int j = 0; j <= iq; j++) {
        __syncthreads();   // previous PV done (and Q load on first iter)

        // Load K and V tiles
#pragma unroll
        for (int u = 0; u < 4; u++) {
            int idx = t + u * 256;
            int row = idx >> 4;
            int c4  = (idx & 15) * 4;
            *(float4*)&Ks[row * 68 + c4] =
                *(const float4*)&K[hb + (j * 64 + row) * DD + c4];
            *(float4*)&Vs[row * 64 + c4] =
                *(const float4*)&V[hb + (j * 64 + row) * DD + c4];
        }
        __syncthreads();

        // S = Q K^T (pre-scaled): 16 columns per thread
        float sv[16];
#pragma unroll
        for (int c = 0; c < 16; c++) sv[c] = 0.f;
#pragma unroll
        for (int k4 = 0; k4 < 16; k4++) {
            float4 qv = *(const float4*)&Qs[r * 68 + k4 * 4];
#pragma unroll
            for (int c4 = 0; c4 < 4; c4++) {
#pragma unroll
                for (int jj = 0; jj < 4; jj++) {
                    int n = c4 * 16 + g * 4 + jj;
                    float4 kv = *(const float4*)&Ks[n * 68 + k4 * 4];
                    float d = qv.x * kv.x + qv.y * kv.y + qv.z * kv.z + qv.w * kv.w;
                    sv[c4 * 4 + jj] += d;
                }
            }
        }

        // Causal mask on diagonal tile
        if (j == iq) {
#pragma unroll
            for (int c4 = 0; c4 < 4; c4++)
#pragma unroll
                for (int jj = 0; jj < 4; jj++) {
                    int kcol = j * 64 + c4 * 16 + g * 4 + jj;
                    if (kcol > qrow) sv[c4 * 4 + jj] = -1e30f;
                }
        }

        // Online softmax: row max over 64 cols (16 local + 4-lane group)
        float mx = m_i;
#pragma unroll
        for (int c = 0; c < 16; c++) mx = fmaxf(mx, sv[c]);
        mx = fmaxf(mx, __shfl_xor_sync(0xffffffffu, mx, 1));
        mx = fmaxf(mx, __shfl_xor_sync(0xffffffffu, mx, 2));
        float corr = __expf(m_i - mx);
        m_i = mx;

        __syncthreads();   // everyone done reading Ks before P overwrite

        float lp = 0.f;
#pragma unroll
        for (int c4 = 0; c4 < 4; c4++)
#pragma unroll
            for (int jj = 0; jj < 4; jj++) {
                float p = __expf(sv[c4 * 4 + jj] - mx);
                lp += p;
                Ks[r * 68 + c4 * 16 + g * 4 + jj] = p;   // P tile
            }
        lp += __shfl_xor_sync(0xffffffffu, lp, 1);
        lp += __shfl_xor_sync(0xffffffffu, lp, 2);
        l_i = l_i * corr + lp;
#pragma unroll
        for (int c = 0; c < 16; c++) o[c] *= corr;

        __syncthreads();   // P visible to all

        // O += P @ V
#pragma unroll
        for (int k4 = 0; k4 < 16; k4++) {
            float4 pv = *(const float4*)&Ks[r * 68 + k4 * 4];
            float pe[4] = {pv.x, pv.y, pv.z, pv.w};
#pragma unroll
            for (int e = 0; e < 4; e++) {
                int kk = k4 * 4 + e;
#pragma unroll
                for (int c4 = 0; c4 < 4; c4++) {
                    float4 vv = *(const float4*)&Vs[kk * 64 + (c4 * 4 + g) * 4];
                    o[c4 * 4 + 0] = fmaf(pe[e], vv.x, o[c4 * 4 + 0]);
                    o[c4 * 4 + 1] = fmaf(pe[e], vv.y, o[c4 * 4 + 1]);
                    o[c4 * 4 + 2] = fmaf(pe[e], vv.z, o[c4 * 4 + 2]);
                    o[c4 * 4 + 3] = fmaf(pe[e], vv.w, o[c4 * 4 + 3]);
                }
            }
        }
    }

    // Normalize and write to A in [B,S,E] layout
    float inv = 1.f / l_i;
    int b_ = bh >> 4;          // / HH
    int h_ = bh & 15;
    float* Ap = A + (b_ * SS + qrow) * EE + h_ * DD;
#pragma unroll
    for (int c4 = 0; c4 < 4; c4++) {
        float4 rv;
        rv.x = o[c4 * 4 + 0] * inv;
        rv.y = o[c4 * 4 + 1] * inv;
        rv.z = o[c4 * 4 + 2] * inv;
        rv.w = o[c4 * 4 + 3] * inv;
        *(float4*)&Ap[c4 * 16 + g * 4] = rv;
    }
}

// ---------------------------------------------------------------------------
extern "C" void kernel_launch(void* const* d_in, const int* in_sizes, int n_in,
                              void* d_out, int out_size)
{
    const float* x  = (const float*)d_in[0];
    // d_in[1] = mask (causal; structure known statically, unused)
    const float* Wq = (const float*)d_in[2];
    const float* bq = (const float*)d_in[3];
    const float* Wk = (const float*)d_in[4];
    const float* bk = (const float*)d_in[5];
    const float* Wv = (const float*)d_in[6];
    const float* bv = (const float*)d_in[7];
    const float* Wo = (const float*)d_in[8];
    const float* bo = (const float*)d_in[9];

    float *Qp, *Kp, *Vp, *Ap;
    cudaGetSymbolAddress((void**)&Qp, g_Q);
    cudaGetSymbolAddress((void**)&Kp, g_K);
    cudaGetSymbolAddress((void**)&Vp, g_V);
    cudaGetSymbolAddress((void**)&Ap, g_A);

    cudaFuncSetAttribute(attn_kernel,
                         cudaFuncAttributeMaxDynamicSharedMemorySize,
                         ATTN_SMEM_BYTES);

    dim3 gg(EE / 128, MM / 128);   // (8, 32)

    sgemm_kernel<1><<<gg, 256>>>(x, Wq, bq, Qp);
    sgemm_kernel<1><<<gg, 256>>>(x, Wk, bk, Kp);
    sgemm_kernel<1><<<gg, 256>>>(x, Wv, bv, Vp);

    rope_kernel<<<(BB * HH * SS * 32) / 256, 256>>>(Qp, Kp);

    attn_kernel<<<dim3(SS / 64, BB * HH), 256, ATTN_SMEM_BYTES>>>(Qp, Kp, Vp, Ap);

    sgemm_kernel<0><<<gg, 256>>>(Ap, Wo, bo, (float*)d_out);
}

// round 4
// speedup vs baseline: 1.2278x; 1.2278x over previous
#include <cuda_runtime.h>
#include <math.h>
#include <stdint.h>

#define BB 2
#define SS 2048
#define EE 1024
#define HH 16
#define DD 64
#define MM (BB*SS)          // 4096 rows for the projection GEMMs

// Scratch (no cudaMalloc allowed)
__device__ __align__(16) float g_Q[BB*HH*SS*DD];
__device__ __align__(16) float g_K[BB*HH*SS*DD];
__device__ __align__(16) float g_V[BB*HH*SS*DD];
__device__ __align__(16) float g_A[BB*SS*EE];

// ---------------------------------------------------------------------------
// tf32 helpers (base sm_103 target: classic mma.sync, no tcgen05)
// ---------------------------------------------------------------------------
__device__ __forceinline__ uint32_t f2tf32(float f) {
    uint32_t u;
    asm("cvt.rna.tf32.f32 %0, %1;" : "=r"(u) : "f"(f));
    return u;
}

__device__ __forceinline__ void mma_tf32(float* d, const uint32_t* a, const uint32_t* b) {
    asm volatile(
        "mma.sync.aligned.m16n8k8.row.col.f32.tf32.tf32.f32 "
        "{%0,%1,%2,%3}, {%4,%5,%6,%7}, {%8,%9}, {%0,%1,%2,%3};\n"
        : "+f"(d[0]), "+f"(d[1]), "+f"(d[2]), "+f"(d[3])
        : "r"(a[0]), "r"(a[1]), "r"(a[2]), "r"(a[3]),
          "r"(b[0]), "r"(b[1]));
}

// [B,H,S,D] scatter address for MODE 1 epilogue
__device__ __forceinline__ float* bhsd_addr(float* out, int row, int col) {
    int b_ = row >> 11;            // / SS
    int s_ = row & (SS - 1);
    int h_ = col >> 6;             // / DD
    int d_ = col & (DD - 1);
    return &out[((size_t)(b_ * HH + h_) * SS + s_) * DD + d_];
}

// ---------------------------------------------------------------------------
// tf32 tensor-core GEMM:  out = X @ W^T + bias
// X:[M,1024] row-major fp32, W:[N,1024] row-major fp32 (nn.Linear).
// CTA tile 128x128, 8 warps of 64x32, K-chunk 32 (4 k8 steps).
// smem stores fragments pre-permuted: A tile [m16k8] -> 128 u32 laid out
// [lane][4 regs] (frag = 1 LDS.128); B tile [n8k8] -> 64 u32 [lane][2 regs]
// (frag = 1 LDS.64).  2 stages, register prefetch, 1 sync per chunk.
// MODE 0: plain [M,EE] output.  MODE 1: scatter to [B,H,S,D].
// ---------------------------------------------------------------------------
#define GEMM_SMEM (2 * 8192 * 4)   // 64 KB

template <int MODE>
__global__ __launch_bounds__(256) void gemm_tf32(
    const float* __restrict__ A, const float* __restrict__ B,
    const float* __restrict__ bias, float* __restrict__ out)
{
    extern __shared__ uint32_t sh[];   // [2][8192]: A 4096 + B 4096 per stage

    const int tid  = threadIdx.x;
    const int lane = tid & 31;
    const int wid  = tid >> 5;
    const int wm   = wid & 1;          // 0..1 -> 64-row half
    const int wn   = wid >> 1;         // 0..3 -> 32-col quarter
    const int bm   = blockIdx.y * 128;
    const int bn   = blockIdx.x * 128;

    const float* Ap = A + (size_t)bm * EE;
    const float* Bp = B + (size_t)bn * EE;

    float d[4][4][4];
#pragma unroll
    for (int mt = 0; mt < 4; mt++)
#pragma unroll
        for (int nt = 0; nt < 4; nt++)
#pragma unroll
            for (int e = 0; e < 4; e++) d[mt][nt][e] = 0.f;

    // Per-thread loader decomposition (same for A and B, constant over chunks)
    // float4 id i = tid + u*256 : row = i>>3 (0..127), c0 = (i&7)*4 (0..28)
    int l_row[4], l_c0[4];
#pragma unroll
    for (int u = 0; u < 4; u++) {
        int i = tid + u * 256;
        l_row[u] = i >> 3;
        l_c0[u]  = (i & 7) * 4;
    }

    // ---- store one chunk's worth of prefetched data into stage s ----
    auto sts_chunk = [&](int s, const float4* pa, const float4* pb) {
        uint32_t* dA = sh + s * 8192;
        uint32_t* dB = dA + 4096;
#pragma unroll
        for (int u = 0; u < 4; u++) {
            int row = l_row[u], c0 = l_c0[u];
            int kt = c0 >> 3;
            {   // A: tile (mt, kt), element rows r, cols c0..c0+3
                int mt = row >> 4, r = row & 15;
                int reg = (r >> 3) + ((c0 & 4) >> 1);
                uint32_t* base = dA + (mt * 4 + kt) * 128 + (r & 7) * 16 + reg;
                base[0]  = f2tf32(pa[u].x);
                base[4]  = f2tf32(pa[u].y);
                base[8]  = f2tf32(pa[u].z);
                base[12] = f2tf32(pa[u].w);
            }
            {   // B: tile (ntile, kt), k rows c0.., col nn
                int ntile = row >> 3, nn = row & 7;
                int reg = (c0 & 4) >> 2;
                uint32_t* base = dB + (ntile * 4 + kt) * 64 + nn * 8 + reg;
                base[0] = f2tf32(pb[u].x);
                base[2] = f2tf32(pb[u].y);
                base[4] = f2tf32(pb[u].z);
                base[6] = f2tf32(pb[u].w);
            }
        }
    };

    // Preload chunk 0 -> stage 0
    {
        float4 pa[4], pb[4];
#pragma unroll
        for (int u = 0; u < 4; u++) {
            pa[u] = *(const float4*)(Ap + (size_t)l_row[u] * EE + l_c0[u]);
            pb[u] = *(const float4*)(Bp + (size_t)l_row[u] * EE + l_c0[u]);
        }
        sts_chunk(0, pa, pb);
    }
    __syncthreads();

    for (int c = 0; c < 32; c++) {
        int s = c & 1;
        float4 pa[4], pb[4];
        if (c < 31) {
            int k0 = (c + 1) * 32;
#pragma unroll
            for (int u = 0; u < 4; u++) {
                pa[u] = *(const float4*)(Ap + (size_t)l_row[u] * EE + k0 + l_c0[u]);
                pb[u] = *(const float4*)(Bp + (size_t)l_row[u] * EE + k0 + l_c0[u]);
            }
        }

        const uint32_t* sA = sh + s * 8192;
        const uint32_t* sB = sA + 4096;
#pragma unroll
        for (int kt = 0; kt < 4; kt++) {
            uint32_t afr[4][4];
            uint32_t bfr[4][2];
#pragma unroll
            for (int mt = 0; mt < 4; mt++)
                *(uint4*)afr[mt] =
                    *(const uint4*)(sA + ((wm * 4 + mt) * 4 + kt) * 128 + lane * 4);
#pragma unroll
            for (int nt = 0; nt < 4; nt++)
                *(uint2*)bfr[nt] =
                    *(const uint2*)(sB + ((wn * 4 + nt) * 4 + kt) * 64 + lane * 2);
#pragma unroll
            for (int mt = 0; mt < 4; mt++)
#pragma unroll
                for (int nt = 0; nt < 4; nt++)
                    mma_tf32(d[mt][nt], afr[mt], bfr[nt]);
        }

        if (c < 31) sts_chunk(1 - s, pa, pb);
        __syncthreads();
    }

    // Epilogue: d0,d1 -> (row0, col..col+1); d2,d3 -> (row0+8, col..col+1)
#pragma unroll
    for (int mt = 0; mt < 4; mt++) {
        int row0 = bm + wm * 64 + mt * 16 + (lane >> 2);
#pragma unroll
        for (int nt = 0; nt < 4; nt++) {
            int col = bn + wn * 32 + nt * 8 + (lane & 3) * 2;
            float bx = bias[col], by = bias[col + 1];
            float2 v0 = make_float2(d[mt][nt][0] + bx, d[mt][nt][1] + by);
            float2 v1 = make_float2(d[mt][nt][2] + bx, d[mt][nt][3] + by);
            if (MODE == 0) {
                *(float2*)&out[(size_t)row0 * EE + col] = v0;
                *(float2*)&out[(size_t)(row0 + 8) * EE + col] = v1;
            } else {
                *(float2*)bhsd_addr(out, row0, col) = v0;
                *(float2*)bhsd_addr(out, row0 + 8, col) = v1;
            }
        }
    }
}

// ---------------------------------------------------------------------------
// RoPE on Q and K in [B,H,S,D] layout.
// ---------------------------------------------------------------------------
__global__ void rope_kernel(float* __restrict__ Q, float* __restrict__ K)
{
    int gid = blockIdx.x * blockDim.x + threadIdx.x;
    int i  = gid & 31;
    int s  = (gid >> 5) & (SS - 1);
    int bh = gid >> 16;
    int base = (bh * SS + s) * DD;

    float freq = exp2f(-(float)i * (13.287712379549449f / 32.0f));
    float ang  = (float)s * freq;
    float sn, cs;
    sincosf(ang, &sn, &cs);

    float q0 = Q[base + i], q1 = Q[base + i + 32];
    Q[base + i]      = q0 * cs - q1 * sn;
    Q[base + i + 32] = q1 * cs + q0 * sn;
    float k0 = K[base + i], k1 = K[base + i + 32];
    K[base + i]      = k0 * cs - k1 * sn;
    K[base + i + 32] = k1 * cs + k0 * sn;
}

// ---------------------------------------------------------------------------
// Flash attention (causal), fp32 SIMT (verified round 1).
// ---------------------------------------------------------------------------
#define ATTN_SMEM_BYTES ((64*68*2 + 64*64) * 4)   // 51200

__global__ __launch_bounds__(256) void attn_kernel(
    const float* __restrict__ Q, const float* __restrict__ K,
    const float* __restrict__ V, float* __restrict__ A)
{
    extern __shared__ float sm[];
    float* Qs = sm;                 // 64 * 68
    float* Ks = sm + 64 * 68;       // 64 * 68 (reused for P)
    float* Vs = sm + 2 * 64 * 68;   // 64 * 64

    int t = threadIdx.x;
    int r = t >> 2;
    int g = t & 3;

    int iq = blockIdx.x;
    int bh = blockIdx.y;
    int hb = bh * SS * DD;
    int q0row = iq * 64;
    int qrow  = q0row + r;

#pragma unroll
    for (int u = 0; u < 4; u++) {
        int idx = t + u * 256;
        int row = idx >> 4;
        int c4  = (idx & 15) * 4;
        float4 v = *(const float4*)&Q[hb + (q0row + row) * DD + c4];
        v.x *= 0.125f; v.y *= 0.125f; v.z *= 0.125f; v.w *= 0.125f;
        *(float4*)&Qs[row * 68 + c4] = v;
    }

    float o[16];
#pragma unroll
    for (int c = 0; c < 16; c++) o[c] = 0.f;
    float m_i = -1e30f, l_i = 0.f;

    for (int j = 0; j <= iq; j++) {
        __syncthreads();

#pragma unroll
        for (int u = 0; u < 4; u++) {
            int idx = t + u * 256;
            int row = idx >> 4;
            int c4  = (idx & 15) * 4;
            *(float4*)&Ks[row * 68 + c4] =
                *(const float4*)&K[hb + (j * 64 + row) * DD + c4];
            *(float4*)&Vs[row * 64 + c4] =
                *(const float4*)&V[hb + (j * 64 + row) * DD + c4];
        }
        __syncthreads();

        float sv[16];
#pragma unroll
        for (int c = 0; c < 16; c++) sv[c] = 0.f;
#pragma unroll
        for (int k4 = 0; k4 < 16; k4++) {
            float4 qv = *(const float4*)&Qs[r * 68 + k4 * 4];
#pragma unroll
            for (int c4 = 0; c4 < 4; c4++) {
#pragma unroll
                for (int jj = 0; jj < 4; jj++) {
                    int n = c4 * 16 + g * 4 + jj;
                    float4 kv = *(const float4*)&Ks[n * 68 + k4 * 4];
                    float dt = qv.x * kv.x + qv.y * kv.y + qv.z * kv.z + qv.w * kv.w;
                    sv[c4 * 4 + jj] += dt;
                }
            }
        }

        if (j == iq) {
#pragma unroll
            for (int c4 = 0; c4 < 4; c4++)
#pragma unroll
                for (int jj = 0; jj < 4; jj++) {
                    int kcol = j * 64 + c4 * 16 + g * 4 + jj;
                    if (kcol > qrow) sv[c4 * 4 + jj] = -1e30f;
                }
        }

        float mx = m_i;
#pragma unroll
        for (int c = 0; c < 16; c++) mx = fmaxf(mx, sv[c]);
        mx = fmaxf(mx, __shfl_xor_sync(0xffffffffu, mx, 1));
        mx = fmaxf(mx, __shfl_xor_sync(0xffffffffu, mx, 2));
        float corr = __expf(m_i - mx);
        m_i = mx;

        __syncthreads();

        float lp = 0.f;
#pragma unroll
        for (int c4 = 0; c4 < 4; c4++)
#pragma unroll
            for (int jj = 0; jj < 4; jj++) {
                float p = __expf(sv[c4 * 4 + jj] - mx);
                lp += p;
                Ks[r * 68 + c4 * 16 + g * 4 + jj] = p;
            }
        lp += __shfl_xor_sync(0xffffffffu, lp, 1);
        lp += __shfl_xor_sync(0xffffffffu, lp, 2);
        l_i = l_i * corr + lp;
#pragma unroll
        for (int c = 0; c < 16; c++) o[c] *= corr;

        __syncthreads();

#pragma unroll
        for (int k4 = 0; k4 < 16; k4++) {
            float4 pv = *(const float4*)&Ks[r * 68 + k4 * 4];
            float pe[4] = {pv.x, pv.y, pv.z, pv.w};
#pragma unroll
            for (int e = 0; e < 4; e++) {
                int kk = k4 * 4 + e;
#pragma unroll
                for (int c4 = 0; c4 < 4; c4++) {
                    float4 vv = *(const float4*)&Vs[kk * 64 + (c4 * 4 + g) * 4];
                    o[c4 * 4 + 0] = fmaf(pe[e], vv.x, o[c4 * 4 + 0]);
                    o[c4 * 4 + 1] = fmaf(pe[e], vv.y, o[c4 * 4 + 1]);
                    o[c4 * 4 + 2] = fmaf(pe[e], vv.z, o[c4 * 4 + 2]);
                    o[c4 * 4 + 3] = fmaf(pe[e], vv.w, o[c4 * 4 + 3]);
                }
            }
        }
    }

    float inv = 1.f / l_i;
    int b_ = bh >> 4;
    int h_ = bh & 15;
    float* Ap = A + (b_ * SS + qrow) * EE + h_ * DD;
#pragma unroll
    for (int c4 = 0; c4 < 4; c4++) {
        float4 rv;
        rv.x = o[c4 * 4 + 0] * inv;
        rv.y = o[c4 * 4 + 1] * inv;
        rv.z = o[c4 * 4 + 2] * inv;
        rv.w = o[c4 * 4 + 3] * inv;
        *(float4*)&Ap[c4 * 16 + g * 4] = rv;
    }
}

// ---------------------------------------------------------------------------
extern "C" void kernel_launch(void* const* d_in, const int* in_sizes, int n_in,
                              void* d_out, int out_size)
{
    const float* x  = (const float*)d_in[0];
    // d_in[1] = mask (causal; structure known statically, unused)
    const float* Wq = (const float*)d_in[2];
    const float* bq = (const float*)d_in[3];
    const float* Wk = (const float*)d_in[4];
    const float* bk = (const float*)d_in[5];
    const float* Wv = (const float*)d_in[6];
    const float* bv = (const float*)d_in[7];
    const float* Wo = (const float*)d_in[8];
    const float* bo = (const float*)d_in[9];

    float *Qp, *Kp, *Vp, *Ap;
    cudaGetSymbolAddress((void**)&Qp, g_Q);
    cudaGetSymbolAddress((void**)&Kp, g_K);
    cudaGetSymbolAddress((void**)&Vp, g_V);
    cudaGetSymbolAddress((void**)&Ap, g_A);

    cudaFuncSetAttribute(gemm_tf32<0>,
                         cudaFuncAttributeMaxDynamicSharedMemorySize, GEMM_SMEM);
    cudaFuncSetAttribute(gemm_tf32<1>,
                         cudaFuncAttributeMaxDynamicSharedMemorySize, GEMM_SMEM);
    cudaFuncSetAttribute(attn_kernel,
                         cudaFuncAttributeMaxDynamicSharedMemorySize, ATTN_SMEM_BYTES);

    dim3 gg(EE / 128, MM / 128);   // (8, 32)

    gemm_tf32<1><<<gg, 256, GEMM_SMEM>>>(x, Wq, bq, Qp);
    gemm_tf32<1><<<gg, 256, GEMM_SMEM>>>(x, Wk, bk, Kp);
    gemm_tf32<1><<<gg, 256, GEMM_SMEM>>>(x, Wv, bv, Vp);

    rope_kernel<<<(BB * HH * SS * 32) / 256, 256>>>(Qp, Kp);

    attn_kernel<<<dim3(SS / 64, BB * HH), 256, ATTN_SMEM_BYTES>>>(Qp, Kp, Vp, Ap);

    gemm_tf32<0><<<gg, 256, GEMM_SMEM>>>(Ap, Wo, bo, (float*)d_out);
}

// round 5
// speedup vs baseline: 3.2829x; 2.6739x over previous
#include <cuda_runtime.h>
#include <math.h>
#include <stdint.h>

#define BB 2
#define SS 2048
#define EE 1024
#define HH 16
#define DD 64
#define MM (BB*SS)          // 4096 rows for the projection GEMMs

// Scratch (no cudaMalloc allowed)
__device__ __align__(16) float g_Q[BB*HH*SS*DD];
__device__ __align__(16) float g_K[BB*HH*SS*DD];
__device__ __align__(16) float g_V[BB*HH*SS*DD];
__device__ __align__(16) float g_A[BB*SS*EE];

// ---------------------------------------------------------------------------
// tf32 helpers (base sm_103 target: classic mma.sync, no tcgen05)
// ---------------------------------------------------------------------------
__device__ __forceinline__ uint32_t f2tf32(float f) {
    uint32_t u;
    asm("cvt.rna.tf32.f32 %0, %1;" : "=r"(u) : "f"(f));
    return u;
}

__device__ __forceinline__ void mma_tf32(float* d, const uint32_t* a, const uint32_t* b) {
    asm volatile(
        "mma.sync.aligned.m16n8k8.row.col.f32.tf32.tf32.f32 "
        "{%0,%1,%2,%3}, {%4,%5,%6,%7}, {%8,%9}, {%0,%1,%2,%3};\n"
        : "+f"(d[0]), "+f"(d[1]), "+f"(d[2]), "+f"(d[3])
        : "r"(a[0]), "r"(a[1]), "r"(a[2]), "r"(a[3]),
          "r"(b[0]), "r"(b[1]));
}

// [B,H,S,D] scatter address for MODE 1 epilogue
__device__ __forceinline__ float* bhsd_addr(float* out, int row, int col) {
    int b_ = row >> 11;            // / SS
    int s_ = row & (SS - 1);
    int h_ = col >> 6;             // / DD
    int d_ = col & (DD - 1);
    return &out[((size_t)(b_ * HH + h_) * SS + s_) * DD + d_];
}

// ---------------------------------------------------------------------------
// tf32 tensor-core GEMM (validated round 4):  out = X @ W^T + bias
// ---------------------------------------------------------------------------
#define GEMM_SMEM (2 * 8192 * 4)   // 64 KB

template <int MODE>
__global__ __launch_bounds__(256) void gemm_tf32(
    const float* __restrict__ A, const float* __restrict__ B,
    const float* __restrict__ bias, float* __restrict__ out)
{
    extern __shared__ uint32_t sh[];   // [2][8192]: A 4096 + B 4096 per stage

    const int tid  = threadIdx.x;
    const int lane = tid & 31;
    const int wid  = tid >> 5;
    const int wm   = wid & 1;
    const int wn   = wid >> 1;
    const int bm   = blockIdx.y * 128;
    const int bn   = blockIdx.x * 128;

    const float* Ap = A + (size_t)bm * EE;
    const float* Bp = B + (size_t)bn * EE;

    float d[4][4][4];
#pragma unroll
    for (int mt = 0; mt < 4; mt++)
#pragma unroll
        for (int nt = 0; nt < 4; nt++)
#pragma unroll
            for (int e = 0; e < 4; e++) d[mt][nt][e] = 0.f;

    int l_row[4], l_c0[4];
#pragma unroll
    for (int u = 0; u < 4; u++) {
        int i = tid + u * 256;
        l_row[u] = i >> 3;
        l_c0[u]  = (i & 7) * 4;
    }

    auto sts_chunk = [&](int s, const float4* pa, const float4* pb) {
        uint32_t* dA = sh + s * 8192;
        uint32_t* dB = dA + 4096;
#pragma unroll
        for (int u = 0; u < 4; u++) {
            int row = l_row[u], c0 = l_c0[u];
            int kt = c0 >> 3;
            {
                int mt = row >> 4, r = row & 15;
                int reg = (r >> 3) + ((c0 & 4) >> 1);
                uint32_t* base = dA + (mt * 4 + kt) * 128 + (r & 7) * 16 + reg;
                base[0]  = f2tf32(pa[u].x);
                base[4]  = f2tf32(pa[u].y);
                base[8]  = f2tf32(pa[u].z);
                base[12] = f2tf32(pa[u].w);
            }
            {
                int ntile = row >> 3, nn = row & 7;
                int reg = (c0 & 4) >> 2;
                uint32_t* base = dB + (ntile * 4 + kt) * 64 + nn * 8 + reg;
                base[0] = f2tf32(pb[u].x);
                base[2] = f2tf32(pb[u].y);
                base[4] = f2tf32(pb[u].z);
                base[6] = f2tf32(pb[u].w);
            }
        }
    };

    {
        float4 pa[4], pb[4];
#pragma unroll
        for (int u = 0; u < 4; u++) {
            pa[u] = *(const float4*)(Ap + (size_t)l_row[u] * EE + l_c0[u]);
            pb[u] = *(const float4*)(Bp + (size_t)l_row[u] * EE + l_c0[u]);
        }
        sts_chunk(0, pa, pb);
    }
    __syncthreads();

    for (int c = 0; c < 32; c++) {
        int s = c & 1;
        float4 pa[4], pb[4];
        if (c < 31) {
            int k0 = (c + 1) * 32;
#pragma unroll
            for (int u = 0; u < 4; u++) {
                pa[u] = *(const float4*)(Ap + (size_t)l_row[u] * EE + k0 + l_c0[u]);
                pb[u] = *(const float4*)(Bp + (size_t)l_row[u] * EE + k0 + l_c0[u]);
            }
        }

        const uint32_t* sA = sh + s * 8192;
        const uint32_t* sB = sA + 4096;
#pragma unroll
        for (int kt = 0; kt < 4; kt++) {
            uint32_t afr[4][4];
            uint32_t bfr[4][2];
#pragma unroll
            for (int mt = 0; mt < 4; mt++)
                *(uint4*)afr[mt] =
                    *(const uint4*)(sA + ((wm * 4 + mt) * 4 + kt) * 128 + lane * 4);
#pragma unroll
            for (int nt = 0; nt < 4; nt++)
                *(uint2*)bfr[nt] =
                    *(const uint2*)(sB + ((wn * 4 + nt) * 4 + kt) * 64 + lane * 2);
#pragma unroll
            for (int mt = 0; mt < 4; mt++)
#pragma unroll
                for (int nt = 0; nt < 4; nt++)
                    mma_tf32(d[mt][nt], afr[mt], bfr[nt]);
        }

        if (c < 31) sts_chunk(1 - s, pa, pb);
        __syncthreads();
    }

#pragma unroll
    for (int mt = 0; mt < 4; mt++) {
        int row0 = bm + wm * 64 + mt * 16 + (lane >> 2);
#pragma unroll
        for (int nt = 0; nt < 4; nt++) {
            int col = bn + wn * 32 + nt * 8 + (lane & 3) * 2;
            float bx = bias[col], by = bias[col + 1];
            float2 v0 = make_float2(d[mt][nt][0] + bx, d[mt][nt][1] + by);
            float2 v1 = make_float2(d[mt][nt][2] + bx, d[mt][nt][3] + by);
            if (MODE == 0) {
                *(float2*)&out[(size_t)row0 * EE + col] = v0;
                *(float2*)&out[(size_t)(row0 + 8) * EE + col] = v1;
            } else {
                *(float2*)bhsd_addr(out, row0, col) = v0;
                *(float2*)bhsd_addr(out, row0 + 8, col) = v1;
            }
        }
    }
}

// ---------------------------------------------------------------------------
// RoPE on Q and K in [B,H,S,D] layout.
// ---------------------------------------------------------------------------
__global__ void rope_kernel(float* __restrict__ Q, float* __restrict__ K)
{
    int gid = blockIdx.x * blockDim.x + threadIdx.x;
    int i  = gid & 31;
    int s  = (gid >> 5) & (SS - 1);
    int bh = gid >> 16;
    int base = (bh * SS + s) * DD;

    float freq = exp2f(-(float)i * (13.287712379549449f / 32.0f));
    float ang  = (float)s * freq;
    float sn, cs;
    sincosf(ang, &sn, &cs);

    float q0 = Q[base + i], q1 = Q[base + i + 32];
    Q[base + i]      = q0 * cs - q1 * sn;
    Q[base + i + 32] = q1 * cs + q0 * sn;
    float k0 = K[base + i], k1 = K[base + i + 32];
    K[base + i]      = k0 * cs - k1 * sn;
    K[base + i + 32] = k1 * cs + k0 * sn;
}

// ---------------------------------------------------------------------------
// Flash attention (causal), tf32 mma.sync.
// CTA: 128 threads (4 warps). Br = Bc = 64.  Warp w owns q rows 16w..16w+15.
// Fragment smem layouts identical to the (validated) GEMM:
//   A tile m16k8 -> 128 u32, frag = uint4 at lane*4
//   B tile n8k8  ->  64 u32, frag = uint2 at lane*2
// Qs: A-op (mt,kt)= (4,8) tiles; Ks: B-op (n=kv,k=d) (8,8); Vs: B-op
// (n=d,k=kv) (8,8); Ps: A-op (4,8) — per-warp private (syncwarp only).
// ---------------------------------------------------------------------------
#define ATTN_SMEM_BYTES (16384 * 4)   // 64 KB: Qs,Ks,Vs,Ps 4096 u32 each

__global__ __launch_bounds__(128) void attn_tf32(
    const float* __restrict__ Q, const float* __restrict__ K,
    const float* __restrict__ V, float* __restrict__ A)
{
    extern __shared__ uint32_t su[];
    uint32_t* Qs = su;            // 4096
    uint32_t* Ks = su + 4096;
    uint32_t* Vs = su + 8192;
    uint32_t* Ps = su + 12288;

    const int tid  = threadIdx.x;
    const int lane = tid & 31;
    const int w    = tid >> 5;

    const int iq = blockIdx.x;          // q tile (64 rows)
    const int bh = blockIdx.y;          // b*H + h
    const int hb = bh * SS * DD;
    const int q0 = iq * 64;

    // ---- stage Q tile as A-fragments, pre-scaled by 1/sqrt(D)=0.125 ----
#pragma unroll
    for (int u = 0; u < 8; u++) {
        int idx = tid + u * 128;        // 0..1023
        int row = idx >> 4;             // 0..63
        int c0  = (idx & 15) * 4;       // 0..60
        float4 v = *(const float4*)&Q[hb + (q0 + row) * DD + c0];
        int mt = row >> 4, kt = c0 >> 3, r = row & 15;
        int reg = (r >> 3) + ((c0 & 4) >> 1);
        uint32_t* b = Qs + (mt * 8 + kt) * 128 + (r & 7) * 16 + reg;
        b[0]  = f2tf32(v.x * 0.125f);
        b[4]  = f2tf32(v.y * 0.125f);
        b[8]  = f2tf32(v.z * 0.125f);
        b[12] = f2tf32(v.w * 0.125f);
    }

    float o[8][4];
#pragma unroll
    for (int nt = 0; nt < 8; nt++)
#pragma unroll
        for (int e = 0; e < 4; e++) o[nt][e] = 0.f;
    float m0 = -1e30f, m1 = -1e30f, l0 = 0.f, l1 = 0.f;

    for (int j = 0; j <= iq; j++) {
        __syncthreads();   // prior iter done with Ks/Vs (and Q staged, iter 0)

        // ---- stage K (B-op: n=kv row, k=d) and V (B-op: n=d, k=kv) ----
#pragma unroll
        for (int u = 0; u < 8; u++) {
            int idx = tid + u * 128;
            int row = idx >> 4;
            int c0  = (idx & 15) * 4;
            float4 kv4 = *(const float4*)&K[hb + (j * 64 + row) * DD + c0];
            {
                int nt = row >> 3, nn = row & 7, kt = c0 >> 3;
                int reg = (c0 & 4) >> 2;
                uint32_t* b = Ks + (nt * 8 + kt) * 64 + nn * 8 + reg;
                b[0] = f2tf32(kv4.x);
                b[2] = f2tf32(kv4.y);
                b[4] = f2tf32(kv4.z);
                b[6] = f2tf32(kv4.w);
            }
            float4 vv4 = *(const float4*)&V[hb + (j * 64 + row) * DD + c0];
            {
                int kt = row >> 3;
                int kreg = (row & 3) * 2 + ((row & 4) >> 2);
                int nt = c0 >> 3;
                int cc = c0 & 7;
                uint32_t* b = Vs + (nt * 8 + kt) * 64 + kreg;
                b[(cc + 0) * 8] = f2tf32(vv4.x);
                b[(cc + 1) * 8] = f2tf32(vv4.y);
                b[(cc + 2) * 8] = f2tf32(vv4.z);
                b[(cc + 3) * 8] = f2tf32(vv4.w);
            }
        }
        __syncthreads();

        // ---- S = Q K^T : warp w rows 16w..16w+15, all 64 cols ----
        float s[8][4];
#pragma unroll
        for (int nt = 0; nt < 8; nt++)
#pragma unroll
            for (int e = 0; e < 4; e++) s[nt][e] = 0.f;
#pragma unroll
        for (int kt = 0; kt < 8; kt++) {
            uint32_t af[4];
            *(uint4*)af = *(const uint4*)(Qs + (w * 8 + kt) * 128 + lane * 4);
#pragma unroll
            for (int nt = 0; nt < 8; nt++) {
                uint32_t bf[2];
                *(uint2*)bf = *(const uint2*)(Ks + (nt * 8 + kt) * 64 + lane * 2);
                mma_tf32(s[nt], af, bf);
            }
        }

        // ---- causal mask on diagonal tile ----
        if (j == iq) {
            int lr = w * 16 + (lane >> 2);       // local row of d0/d1
#pragma unroll
            for (int nt = 0; nt < 8; nt++) {
                int lc = nt * 8 + (lane & 3) * 2;
                if (lc > lr)     s[nt][0] = -1e30f;
                if (lc + 1 > lr) s[nt][1] = -1e30f;
                if (lc > lr + 8)     s[nt][2] = -1e30f;
                if (lc + 1 > lr + 8) s[nt][3] = -1e30f;
            }
        }

        // ---- online softmax (rows r0 = lane>>2 and r0+8 of the warp slab) --
        float mx0 = m0, mx1 = m1;
#pragma unroll
        for (int nt = 0; nt < 8; nt++) {
            mx0 = fmaxf(mx0, fmaxf(s[nt][0], s[nt][1]));
            mx1 = fmaxf(mx1, fmaxf(s[nt][2], s[nt][3]));
        }
        mx0 = fmaxf(mx0, __shfl_xor_sync(0xffffffffu, mx0, 1));
        mx0 = fmaxf(mx0, __shfl_xor_sync(0xffffffffu, mx0, 2));
        mx1 = fmaxf(mx1, __shfl_xor_sync(0xffffffffu, mx1, 1));
        mx1 = fmaxf(mx1, __shfl_xor_sync(0xffffffffu, mx1, 2));
        float corr0 = __expf(m0 - mx0);
        float corr1 = __expf(m1 - mx1);
        m0 = mx0; m1 = mx1;

        // p = exp(s - m), store as tf32 A-fragments into warp-private Ps
        int r0 = lane >> 2;
        int k0i = (lane & 3) * 2;
        int ka = (k0i & 3) * 4 + ((k0i & 4) >> 1);            // k0 column slot
        int kb = ((k0i + 1) & 3) * 4 + (((k0i + 1) & 4) >> 1);
        float lp0 = 0.f, lp1 = 0.f;
#pragma unroll
        for (int nt = 0; nt < 8; nt++) {
            float p00 = __expf(s[nt][0] - mx0);
            float p01 = __expf(s[nt][1] - mx0);
            float p10 = __expf(s[nt][2] - mx1);
            float p11 = __expf(s[nt][3] - mx1);
            lp0 += p00 + p01;
            lp1 += p10 + p11;
            uint32_t* pw = Ps + (w * 8 + nt) * 128 + r0 * 16;
            pw[ka]     = f2tf32(p00);
            pw[kb]     = f2tf32(p01);
            pw[ka + 1] = f2tf32(p10);
            pw[kb + 1] = f2tf32(p11);
        }
        lp0 += __shfl_xor_sync(0xffffffffu, lp0, 1);
        lp0 += __shfl_xor_sync(0xffffffffu, lp0, 2);
        lp1 += __shfl_xor_sync(0xffffffffu, lp1, 1);
        lp1 += __shfl_xor_sync(0xffffffffu, lp1, 2);
        l0 = l0 * corr0 + lp0;
        l1 = l1 * corr1 + lp1;

        // rescale O
#pragma unroll
        for (int nt = 0; nt < 8; nt++) {
            o[nt][0] *= corr0; o[nt][1] *= corr0;
            o[nt][2] *= corr1; o[nt][3] *= corr1;
        }

        __syncwarp();   // Ps tile (warp-private) visible within warp

        // ---- O += P @ V ----
#pragma unroll
        for (int kt = 0; kt < 8; kt++) {
            uint32_t af[4];
            *(uint4*)af = *(const uint4*)(Ps + (w * 8 + kt) * 128 + lane * 4);
#pragma unroll
            for (int nt = 0; nt < 8; nt++) {
                uint32_t bf[2];
                *(uint2*)bf = *(const uint2*)(Vs + (nt * 8 + kt) * 64 + lane * 2);
                mma_tf32(o[nt], af, bf);
            }
        }
    }

    // ---- normalize + write to A [B,S,E] ----
    float inv0 = 1.f / l0;
    float inv1 = 1.f / l1;
    int b_ = bh >> 4;
    int h_ = bh & 15;
    int row0 = q0 + w * 16 + (lane >> 2);
#pragma unroll
    for (int nt = 0; nt < 8; nt++) {
        int col = h_ * DD + nt * 8 + (lane & 3) * 2;
        float2 v0 = make_float2(o[nt][0] * inv0, o[nt][1] * inv0);
        float2 v1 = make_float2(o[nt][2] * inv1, o[nt][3] * inv1);
        *(float2*)&A[(size_t)(b_ * SS + row0) * EE + col] = v0;
        *(float2*)&A[(size_t)(b_ * SS + row0 + 8) * EE + col] = v1;
    }
}

// ---------------------------------------------------------------------------
extern "C" void kernel_launch(void* const* d_in, const int* in_sizes, int n_in,
                              void* d_out, int out_size)
{
    const float* x  = (const float*)d_in[0];
    // d_in[1] = mask (causal; structure known statically, unused)
    const float* Wq = (const float*)d_in[2];
    const float* bq = (const float*)d_in[3];
    const float* Wk = (const float*)d_in[4];
    const float* bk = (const float*)d_in[5];
    const float* Wv = (const float*)d_in[6];
    const float* bv = (const float*)d_in[7];
    const float* Wo = (const float*)d_in[8];
    const float* bo = (const float*)d_in[9];

    float *Qp, *Kp, *Vp, *Ap;
    cudaGetSymbolAddress((void**)&Qp, g_Q);
    cudaGetSymbolAddress((void**)&Kp, g_K);
    cudaGetSymbolAddress((void**)&Vp, g_V);
    cudaGetSymbolAddress((void**)&Ap, g_A);

    cudaFuncSetAttribute(gemm_tf32<0>,
                         cudaFuncAttributeMaxDynamicSharedMemorySize, GEMM_SMEM);
    cudaFuncSetAttribute(gemm_tf32<1>,
                         cudaFuncAttributeMaxDynamicSharedMemorySize, GEMM_SMEM);
    cudaFuncSetAttribute(attn_tf32,
                         cudaFuncAttributeMaxDynamicSharedMemorySize, ATTN_SMEM_BYTES);

    dim3 gg(EE / 128, MM / 128);   // (8, 32)

    gemm_tf32<1><<<gg, 256, GEMM_SMEM>>>(x, Wq, bq, Qp);
    gemm_tf32<1><<<gg, 256, GEMM_SMEM>>>(x, Wk, bk, Kp);
    gemm_tf32<1><<<gg, 256, GEMM_SMEM>>>(x, Wv, bv, Vp);

    rope_kernel<<<(BB * HH * SS * 32) / 256, 256>>>(Qp, Kp);

    attn_tf32<<<dim3(SS / 64, BB * HH), 128, ATTN_SMEM_BYTES>>>(Qp, Kp, Vp, Ap);

    gemm_tf32<0><<<gg, 256, GEMM_SMEM>>>(Ap, Wo, bo, (float*)d_out);
}

// round 6
// speedup vs baseline: 6.1479x; 1.8727x over previous
#include <cuda_runtime.h>
#include <cuda_fp16.h>
#include <math.h>
#include <stdint.h>

#define BB 2
#define SS 2048
#define EE 1024
#define HH 16
#define DD 64
#define MM (BB*SS)          // 4096 rows for the projection GEMMs

// Scratch (no cudaMalloc allowed)
__device__ __align__(16) float g_Q[BB*HH*SS*DD];
__device__ __align__(16) float g_K[BB*HH*SS*DD];
__device__ __align__(16) float g_V[BB*HH*SS*DD];
__device__ __align__(16) float g_A[BB*SS*EE];

// ---------------------------------------------------------------------------
// fp16 helpers (classic mma.sync m16n8k16, f32 accumulate)
// ---------------------------------------------------------------------------
__device__ __forceinline__ uint32_t pack_h2(float lo, float hi) {
    uint32_t u;
    asm("cvt.rn.f16x2.f32 %0, %1, %2;" : "=r"(u) : "f"(hi), "f"(lo));
    return u;
}

__device__ __forceinline__ void mma_f16(float* d, const uint32_t* a, const uint32_t* b) {
    asm volatile(
        "mma.sync.aligned.m16n8k16.row.col.f32.f16.f16.f32 "
        "{%0,%1,%2,%3}, {%4,%5,%6,%7}, {%8,%9}, {%0,%1,%2,%3};\n"
        : "+f"(d[0]), "+f"(d[1]), "+f"(d[2]), "+f"(d[3])
        : "r"(a[0]), "r"(a[1]), "r"(a[2]), "r"(a[3]),
          "r"(b[0]), "r"(b[1]));
}

// [B,H,S,D] scatter address for MODE 1 epilogue
__device__ __forceinline__ float* bhsd_addr(float* out, int row, int col) {
    int b_ = row >> 11;            // / SS
    int s_ = row & (SS - 1);
    int h_ = col >> 6;             // / DD
    int d_ = col & (DD - 1);
    return &out[((size_t)(b_ * HH + h_) * SS + s_) * DD + d_];
}

// ---------------------------------------------------------------------------
// fp16 tensor-core GEMM:  out = X @ W^T + bias
// X:[M,1024] row-major fp32, W:[N,1024] row-major fp32 (nn.Linear).
// CTA tile 128x128, 8 warps of 64x32, K-chunk 32 (2 k16 steps).
// smem holds half2 fragment-major tiles:
//   A tile m16k16 -> 128 u32, frag = uint4 at lane*4
//   B tile n8k16  ->  64 u32, frag = uint2 at lane*2
// frag mapping (m16n8k16): A lane=(r&7)*4+((k&7)>>1), reg=(r>>3)+((k>>3)<<1),
// half=k&1; B lane=n*4+((k&7)>>1), reg=k>>3, half=k&1.
// 2 stages, register prefetch, 1 sync per chunk.
// ---------------------------------------------------------------------------
#define GEMM_SMEM (2 * 4096 * 4)   // 32 KB: per stage A 2048 u32 + B 2048 u32

template <int MODE>
__global__ __launch_bounds__(256) void gemm_f16(
    const float* __restrict__ A, const float* __restrict__ B,
    const float* __restrict__ bias, float* __restrict__ out)
{
    extern __shared__ uint32_t sh[];

    const int tid  = threadIdx.x;
    const int lane = tid & 31;
    const int wid  = tid >> 5;
    const int wm   = wid & 1;          // 64-row half
    const int wn   = wid >> 1;         // 32-col quarter
    const int bm   = blockIdx.y * 128;
    const int bn   = blockIdx.x * 128;

    const float* Ap = A + (size_t)bm * EE;
    const float* Bp = B + (size_t)bn * EE;

    float d[4][4][4];
#pragma unroll
    for (int mt = 0; mt < 4; mt++)
#pragma unroll
        for (int nt = 0; nt < 4; nt++)
#pragma unroll
            for (int e = 0; e < 4; e++) d[mt][nt][e] = 0.f;

    // loader decomposition: idx = tid + u*256 -> row (0..127), c0 = (idx&7)*4
    int l_row[4], l_c0[4];
#pragma unroll
    for (int u = 0; u < 4; u++) {
        int i = tid + u * 256;
        l_row[u] = i >> 3;
        l_c0[u]  = (i & 7) * 4;
    }

    auto sts_chunk = [&](int s, const float4* pa, const float4* pb) {
        uint32_t* dA = sh + s * 4096;
        uint32_t* dB = dA + 2048;
#pragma unroll
        for (int u = 0; u < 4; u++) {
            int row = l_row[u], c0 = l_c0[u];
            int kt = c0 >> 4, kl = c0 & 15;
            {   // A fragment store: pairs (kl,kl+1) and (kl+2,kl+3)
                int mt = row >> 4, r = row & 15;
                int fi = ((r & 7) * 4 + ((kl & 7) >> 1)) * 4
                         + (r >> 3) + ((kl >> 3) << 1);
                uint32_t* base = dA + (mt * 2 + kt) * 128 + fi;
                base[0] = pack_h2(pa[u].x, pa[u].y);
                base[4] = pack_h2(pa[u].z, pa[u].w);
            }
            {   // B fragment store
                int ntile = row >> 3, nn = row & 7;
                int bi = (nn * 4 + ((kl & 7) >> 1)) * 2 + (kl >> 3);
                uint32_t* base = dB + (ntile * 2 + kt) * 64 + bi;
                base[0] = pack_h2(pb[u].x, pb[u].y);
                base[2] = pack_h2(pb[u].z, pb[u].w);
            }
        }
    };

    {
        float4 pa[4], pb[4];
#pragma unroll
        for (int u = 0; u < 4; u++) {
            pa[u] = *(const float4*)(Ap + (size_t)l_row[u] * EE + l_c0[u]);
            pb[u] = *(const float4*)(Bp + (size_t)l_row[u] * EE + l_c0[u]);
        }
        sts_chunk(0, pa, pb);
    }
    __syncthreads();

    for (int c = 0; c < 32; c++) {
        int s = c & 1;
        float4 pa[4], pb[4];
        if (c < 31) {
            int k0 = (c + 1) * 32;
#pragma unroll
            for (int u = 0; u < 4; u++) {
                pa[u] = *(const float4*)(Ap + (size_t)l_row[u] * EE + k0 + l_c0[u]);
                pb[u] = *(const float4*)(Bp + (size_t)l_row[u] * EE + k0 + l_c0[u]);
            }
        }

        const uint32_t* sA = sh + s * 4096;
        const uint32_t* sB = sA + 2048;
#pragma unroll
        for (int kt = 0; kt < 2; kt++) {
            uint32_t afr[4][4];
            uint32_t bfr[4][2];
#pragma unroll
            for (int mt = 0; mt < 4; mt++)
                *(uint4*)afr[mt] =
                    *(const uint4*)(sA + ((wm * 4 + mt) * 2 + kt) * 128 + lane * 4);
#pragma unroll
            for (int nt = 0; nt < 4; nt++)
                *(uint2*)bfr[nt] =
                    *(const uint2*)(sB + ((wn * 4 + nt) * 2 + kt) * 64 + lane * 2);
#pragma unroll
            for (int mt = 0; mt < 4; mt++)
#pragma unroll
                for (int nt = 0; nt < 4; nt++)
                    mma_f16(d[mt][nt], afr[mt], bfr[nt]);
        }

        if (c < 31) sts_chunk(1 - s, pa, pb);
        __syncthreads();
    }

#pragma unroll
    for (int mt = 0; mt < 4; mt++) {
        int row0 = bm + wm * 64 + mt * 16 + (lane >> 2);
#pragma unroll
        for (int nt = 0; nt < 4; nt++) {
            int col = bn + wn * 32 + nt * 8 + (lane & 3) * 2;
            float bx = bias[col], by = bias[col + 1];
            float2 v0 = make_float2(d[mt][nt][0] + bx, d[mt][nt][1] + by);
            float2 v1 = make_float2(d[mt][nt][2] + bx, d[mt][nt][3] + by);
            if (MODE == 0) {
                *(float2*)&out[(size_t)row0 * EE + col] = v0;
                *(float2*)&out[(size_t)(row0 + 8) * EE + col] = v1;
            } else {
                *(float2*)bhsd_addr(out, row0, col) = v0;
                *(float2*)bhsd_addr(out, row0 + 8, col) = v1;
            }
        }
    }
}

// ---------------------------------------------------------------------------
// RoPE on Q and K in [B,H,S,D] layout.
// ---------------------------------------------------------------------------
__global__ void rope_kernel(float* __restrict__ Q, float* __restrict__ K)
{
    int gid = blockIdx.x * blockDim.x + threadIdx.x;
    int i  = gid & 31;
    int s  = (gid >> 5) & (SS - 1);
    int bh = gid >> 16;
    int base = (bh * SS + s) * DD;

    float freq = exp2f(-(float)i * (13.287712379549449f / 32.0f));
    float ang  = (float)s * freq;
    float sn, cs;
    sincosf(ang, &sn, &cs);

    float q0 = Q[base + i], q1 = Q[base + i + 32];
    Q[base + i]      = q0 * cs - q1 * sn;
    Q[base + i + 32] = q1 * cs + q0 * sn;
    float k0 = K[base + i], k1 = K[base + i + 32];
    K[base + i]      = k0 * cs - k1 * sn;
    K[base + i + 32] = k1 * cs + k0 * sn;
}

// ---------------------------------------------------------------------------
// Flash attention (causal), fp16 mma.sync m16n8k16.
// CTA: 128 threads (4 warps). Br = Bc = 64. Warp w owns q rows 16w..16w+15.
// Qs: A-frags (4 mt x 4 kt tiles, 128 u32 each); Ks: B-frags n=kv (8 x 4);
// Vs: B-frags n=d, k=kv (8 x 4).  P stays in registers (S-frag layout ==
// PV A-operand layout for m16n8k16).
// ---------------------------------------------------------------------------
#define ATTN_SMEM_BYTES (3 * 2048 * 4)   // 24 KB

__global__ __launch_bounds__(128) void attn_f16(
    const float* __restrict__ Q, const float* __restrict__ K,
    const float* __restrict__ V, float* __restrict__ A)
{
    extern __shared__ uint32_t su[];
    uint32_t* Qs = su;            // 2048
    uint32_t* Ks = su + 2048;
    uint32_t* Vs = su + 4096;

    const int tid  = threadIdx.x;
    const int lane = tid & 31;
    const int w    = tid >> 5;

    const int iq = blockIdx.x;          // q tile (64 rows)
    const int bh = blockIdx.y;          // b*H + h
    const int hb = bh * SS * DD;
    const int q0 = iq * 64;

    // ---- stage Q tile as A-fragments, pre-scaled by 1/sqrt(D)=0.125 ----
#pragma unroll
    for (int u = 0; u < 8; u++) {
        int idx = tid + u * 128;        // 0..1023
        int row = idx >> 4;             // 0..63
        int c0  = (idx & 15) * 4;       // 0..60
        float4 v = *(const float4*)&Q[hb + (q0 + row) * DD + c0];
        int mt = row >> 4, r = row & 15, kt = c0 >> 4, kl = c0 & 15;
        int fi = ((r & 7) * 4 + ((kl & 7) >> 1)) * 4
                 + (r >> 3) + ((kl >> 3) << 1);
        uint32_t* b = Qs + (mt * 4 + kt) * 128 + fi;
        b[0] = pack_h2(v.x * 0.125f, v.y * 0.125f);
        b[4] = pack_h2(v.z * 0.125f, v.w * 0.125f);
    }

    float o[8][4];
#pragma unroll
    for (int nt = 0; nt < 8; nt++)
#pragma unroll
        for (int e = 0; e < 4; e++) o[nt][e] = 0.f;
    float m0 = -1e30f, m1 = -1e30f, l0 = 0.f, l1 = 0.f;

    for (int j = 0; j <= iq; j++) {
        __syncthreads();   // prior iter done with Ks/Vs (and Q staged, iter 0)

        // ---- stage K (B-op: n=kv, k=d) ----
#pragma unroll
        for (int u = 0; u < 8; u++) {
            int idx = tid + u * 128;
            int row = idx >> 4;          // kv row
            int c0  = (idx & 15) * 4;    // d
            float4 kv4 = *(const float4*)&K[hb + (j * 64 + row) * DD + c0];
            int ntile = row >> 3, nn = row & 7, kt = c0 >> 4, kl = c0 & 15;
            int bi = (nn * 4 + ((kl & 7) >> 1)) * 2 + (kl >> 3);
            uint32_t* b = Ks + (ntile * 4 + kt) * 64 + bi;
            b[0] = pack_h2(kv4.x, kv4.y);
            b[2] = pack_h2(kv4.z, kv4.w);
        }
        // ---- stage V (B-op: n=d, k=kv): pack kv row-pairs into half2 ----
#pragma unroll
        for (int u = 0; u < 4; u++) {
            int idx = tid + u * 128;     // 0..511
            int pr  = idx >> 4;          // kv pair 0..31
            int c0  = (idx & 15) * 4;    // d
            int kv0 = pr * 2;
            float4 a4 = *(const float4*)&V[hb + (j * 64 + kv0) * DD + c0];
            float4 b4 = *(const float4*)&V[hb + (j * 64 + kv0 + 1) * DD + c0];
            int kt = kv0 >> 4, kl = kv0 & 15;
            int hp = (kl & 7) >> 1, reg = kl >> 3;
            int ntile = c0 >> 3, nn = c0 & 7;
            uint32_t* b = Vs + (ntile * 4 + kt) * 64;
            b[(nn + 0) * 8 + hp * 2 + reg] = pack_h2(a4.x, b4.x);
            b[(nn + 1) * 8 + hp * 2 + reg] = pack_h2(a4.y, b4.y);
            b[(nn + 2) * 8 + hp * 2 + reg] = pack_h2(a4.z, b4.z);
            b[(nn + 3) * 8 + hp * 2 + reg] = pack_h2(a4.w, b4.w);
        }
        __syncthreads();

        // ---- S = Q K^T : warp w rows 16w..16w+15, all 64 cols ----
        float s[8][4];
#pragma unroll
        for (int nt = 0; nt < 8; nt++)
#pragma unroll
            for (int e = 0; e < 4; e++) s[nt][e] = 0.f;
#pragma unroll
        for (int kt = 0; kt < 4; kt++) {
            uint32_t af[4];
            *(uint4*)af = *(const uint4*)(Qs + (w * 4 + kt) * 128 + lane * 4);
#pragma unroll
            for (int nt = 0; nt < 8; nt++) {
                uint32_t bf[2];
                *(uint2*)bf = *(const uint2*)(Ks + (nt * 4 + kt) * 64 + lane * 2);
                mma_f16(s[nt], af, bf);
            }
        }

        // ---- causal mask on diagonal tile ----
        if (j == iq) {
            int lr = w * 16 + (lane >> 2);
#pragma unroll
            for (int nt = 0; nt < 8; nt++) {
                int lc = nt * 8 + (lane & 3) * 2;
                if (lc > lr)     s[nt][0] = -1e30f;
                if (lc + 1 > lr) s[nt][1] = -1e30f;
                if (lc > lr + 8)     s[nt][2] = -1e30f;
                if (lc + 1 > lr + 8) s[nt][3] = -1e30f;
            }
        }

        // ---- online softmax (rows lane>>2 and +8 of the warp slab) ----
        float mx0 = m0, mx1 = m1;
#pragma unroll
        for (int nt = 0; nt < 8; nt++) {
            mx0 = fmaxf(mx0, fmaxf(s[nt][0], s[nt][1]));
            mx1 = fmaxf(mx1, fmaxf(s[nt][2], s[nt][3]));
        }
        mx0 = fmaxf(mx0, __shfl_xor_sync(0xffffffffu, mx0, 1));
        mx0 = fmaxf(mx0, __shfl_xor_sync(0xffffffffu, mx0, 2));
        mx1 = fmaxf(mx1, __shfl_xor_sync(0xffffffffu, mx1, 1));
        mx1 = fmaxf(mx1, __shfl_xor_sync(0xffffffffu, mx1, 2));
        float corr0 = __expf(m0 - mx0);
        float corr1 = __expf(m1 - mx1);
        m0 = mx0; m1 = mx1;

        // p = exp(s-m) -> fp16 A-fragments, entirely in registers
        uint32_t ap[4][4];
        float lp0 = 0.f, lp1 = 0.f;
#pragma unroll
        for (int nt = 0; nt < 8; nt++) {
            float p00 = __expf(s[nt][0] - mx0);
            float p01 = __expf(s[nt][1] - mx0);
            float p10 = __expf(s[nt][2] - mx1);
            float p11 = __expf(s[nt][3] - mx1);
            lp0 += p00 + p01;
            lp1 += p10 + p11;
            int kt = nt >> 1, h = (nt & 1) * 2;
            ap[kt][h]     = pack_h2(p00, p01);
            ap[kt][h + 1] = pack_h2(p10, p11);
        }
        lp0 += __shfl_xor_sync(0xffffffffu, lp0, 1);
        lp0 += __shfl_xor_sync(0xffffffffu, lp0, 2);
        lp1 += __shfl_xor_sync(0xffffffffu, lp1, 1);
        lp1 += __shfl_xor_sync(0xffffffffu, lp1, 2);
        l0 = l0 * corr0 + lp0;
        l1 = l1 * corr1 + lp1;

#pragma unroll
        for (int nt = 0; nt < 8; nt++) {
            o[nt][0] *= corr0; o[nt][1] *= corr0;
            o[nt][2] *= corr1; o[nt][3] *= corr1;
        }

        // ---- O += P @ V ----
#pragma unroll
        for (int kt = 0; kt < 4; kt++) {
#pragma unroll
            for (int nt = 0; nt < 8; nt++) {
                uint32_t bf[2];
                *(uint2*)bf = *(const uint2*)(Vs + (nt * 4 + kt) * 64 + lane * 2);
                mma_f16(o[nt], ap[kt], bf);
            }
        }
    }

    // ---- normalize + write to A [B,S,E] ----
    float inv0 = 1.f / l0;
    float inv1 = 1.f / l1;
    int b_ = bh >> 4;
    int h_ = bh & 15;
    int row0 = q0 + w * 16 + (lane >> 2);
#pragma unroll
    for (int nt = 0; nt < 8; nt++) {
        int col = h_ * DD + nt * 8 + (lane & 3) * 2;
        float2 v0 = make_float2(o[nt][0] * inv0, o[nt][1] * inv0);
        float2 v1 = make_float2(o[nt][2] * inv1, o[nt][3] * inv1);
        *(float2*)&A[(size_t)(b_ * SS + row0) * EE + col] = v0;
        *(float2*)&A[(size_t)(b_ * SS + row0 + 8) * EE + col] = v1;
    }
}

// ---------------------------------------------------------------------------
extern "C" void kernel_launch(void* const* d_in, const int* in_sizes, int n_in,
                              void* d_out, int out_size)
{
    const float* x  = (const float*)d_in[0];
    // d_in[1] = mask (causal; structure known statically, unused)
    const float* Wq = (const float*)d_in[2];
    const float* bq = (const float*)d_in[3];
    const float* Wk = (const float*)d_in[4];
    const float* bk = (const float*)d_in[5];
    const float* Wv = (const float*)d_in[6];
    const float* bv = (const float*)d_in[7];
    const float* Wo = (const float*)d_in[8];
    const float* bo = (const float*)d_in[9];

    float *Qp, *Kp, *Vp, *Ap;
    cudaGetSymbolAddress((void**)&Qp, g_Q);
    cudaGetSymbolAddress((void**)&Kp, g_K);
    cudaGetSymbolAddress((void**)&Vp, g_V);
    cudaGetSymbolAddress((void**)&Ap, g_A);

    cudaFuncSetAttribute(gemm_f16<0>,
                         cudaFuncAttributeMaxDynamicSharedMemorySize, GEMM_SMEM);
    cudaFuncSetAttribute(gemm_f16<1>,
                         cudaFuncAttributeMaxDynamicSharedMemorySize, GEMM_SMEM);
    cudaFuncSetAttribute(attn_f16,
                         cudaFuncAttributeMaxDynamicSharedMemorySize, ATTN_SMEM_BYTES);

    dim3 gg(EE / 128, MM / 128);   // (8, 32)

    gemm_f16<1><<<gg, 256, GEMM_SMEM>>>(x, Wq, bq, Qp);
    gemm_f16<1><<<gg, 256, GEMM_SMEM>>>(x, Wk, bk, Kp);
    gemm_f16<1><<<gg, 256, GEMM_SMEM>>>(x, Wv, bv, Vp);

    rope_kernel<<<(BB * HH * SS * 32) / 256, 256>>>(Qp, Kp);

    attn_f16<<<dim3(SS / 64, BB * HH), 128, ATTN_SMEM_BYTES>>>(Qp, Kp, Vp, Ap);

    gemm_f16<0><<<gg, 256, GEMM_SMEM>>>(Ap, Wo, bo, (float*)d_out);
}

// round 11
// speedup vs baseline: 6.9849x; 1.1361x over previous
#include <cuda_runtime.h>
#include <cuda_fp16.h>
#include <math.h>
#include <stdint.h>

#define BB 2
#define SS 2048
#define EE 1024
#define HH 16
#define DD 64
#define MM (BB*SS)          // 4096 rows for the projection GEMMs

// Scratch (no cudaMalloc allowed)
__device__ __align__(16) float g_Q[BB*HH*SS*DD];
__device__ __align__(16) float g_K[BB*HH*SS*DD];
__device__ __align__(16) float g_V[BB*HH*SS*DD];
__device__ __align__(16) float g_A[BB*SS*EE];

// ---------------------------------------------------------------------------
// fp16 helpers (classic mma.sync m16n8k16, f32 accumulate)
// ---------------------------------------------------------------------------
__device__ __forceinline__ uint32_t pack_h2(float lo, float hi) {
    uint32_t u;
    asm("cvt.rn.f16x2.f32 %0, %1, %2;" : "=r"(u) : "f"(hi), "f"(lo));
    return u;
}

__device__ __forceinline__ void mma_f16(float* d, const uint32_t* a, const uint32_t* b) {
    asm volatile(
        "mma.sync.aligned.m16n8k16.row.col.f32.f16.f16.f32 "
        "{%0,%1,%2,%3}, {%4,%5,%6,%7}, {%8,%9}, {%0,%1,%2,%3};\n"
        : "+f"(d[0]), "+f"(d[1]), "+f"(d[2]), "+f"(d[3])
        : "r"(a[0]), "r"(a[1]), "r"(a[2]), "r"(a[3]),
          "r"(b[0]), "r"(b[1]));
}

// [B,H,S,D] scatter address for MODE 1 epilogue
__device__ __forceinline__ float* bhsd_addr(float* out, int row, int col) {
    int b_ = row >> 11;            // / SS
    int s_ = row & (SS - 1);
    int h_ = col >> 6;             // / DD
    int d_ = col & (DD - 1);
    return &out[((size_t)(b_ * HH + h_) * SS + s_) * DD + d_];
}

// ---------------------------------------------------------------------------
// fp16 tensor-core GEMM v2:  out = X @ W^T + bias
// 128 threads (4 warps), CTA tile 128x128, warp tile 64x64 (mt 0..3, nt 0..7),
// K-chunk 32 (2 k16 steps), 2-stage smem, prefetch converted to packed half2
// in registers.  blockIdx.z selects (W, bias, out) -> QKV fused in 1 launch.
// Fragment layouts identical to validated round-6 kernel:
//   A tile m16k16 -> 128 u32, frag = uint4 at lane*4
//   B tile n8k16  ->  64 u32, frag = uint2 at lane*2
// MODE 0: plain [M,EE] output.  MODE 1: scatter to [B,H,S,D].
// ---------------------------------------------------------------------------
#define GEMM_SMEM (2 * 4096 * 4)   // 32 KB: per stage A 2048 u32 + B 2048 u32

template <int MODE>
__global__ __launch_bounds__(128) void gemm_f16v2(
    const float* __restrict__ X,
    const float* __restrict__ W0, const float* __restrict__ W1,
    const float* __restrict__ W2,
    const float* __restrict__ b0, const float* __restrict__ b1,
    const float* __restrict__ b2,
    float* __restrict__ o0, float* __restrict__ o1, float* __restrict__ o2)
{
    extern __shared__ uint32_t sh[];

    const int tid  = threadIdx.x;
    const int lane = tid & 31;
    const int wid  = tid >> 5;
    const int wm   = wid & 1;          // 64-row half
    const int wn   = wid >> 1;         // 64-col half
    const int bm   = blockIdx.y * 128;
    const int bn   = blockIdx.x * 128;

    const float* B_  = (blockIdx.z == 0) ? W0 : (blockIdx.z == 1) ? W1 : W2;
    const float* bias = (blockIdx.z == 0) ? b0 : (blockIdx.z == 1) ? b1 : b2;
    float* out = (blockIdx.z == 0) ? o0 : (blockIdx.z == 1) ? o1 : o2;

    const float* Ap = X  + (size_t)bm * EE;
    const float* Bp = B_ + (size_t)bn * EE;

    float d[4][8][4];
#pragma unroll
    for (int mt = 0; mt < 4; mt++)
#pragma unroll
        for (int nt = 0; nt < 8; nt++)
#pragma unroll
            for (int e = 0; e < 4; e++) d[mt][nt][e] = 0.f;

    // loader: 2048 float4 per chunk (A 1024 + B 1024), 16 per thread.
    // id = tid + u*128: row = id>>3, c0=(id&7)*4
    int l_row[8], l_c0[8];
#pragma unroll
    for (int u = 0; u < 8; u++) {
        int i = tid + u * 128;
        l_row[u] = i >> 3;
        l_c0[u]  = (i & 7) * 4;
    }

    // prefetch one chunk -> packed half2 regs
    uint32_t pa[8][2], pb[8][2];
    auto prefetch = [&](int k0) {
#pragma unroll
        for (int u = 0; u < 8; u++) {
            float4 v = *(const float4*)(Ap + (size_t)l_row[u] * EE + k0 + l_c0[u]);
            pa[u][0] = pack_h2(v.x, v.y);
            pa[u][1] = pack_h2(v.z, v.w);
        }
#pragma unroll
        for (int u = 0; u < 8; u++) {
            float4 v = *(const float4*)(Bp + (size_t)l_row[u] * EE + k0 + l_c0[u]);
            pb[u][0] = pack_h2(v.x, v.y);
            pb[u][1] = pack_h2(v.z, v.w);
        }
    };

    auto sts_chunk = [&](int s) {
        uint32_t* dA = sh + s * 4096;
        uint32_t* dB = dA + 2048;
#pragma unroll
        for (int u = 0; u < 8; u++) {
            int row = l_row[u], c0 = l_c0[u];
            int kt = c0 >> 4, kl = c0 & 15;
            // A fragment slots for pairs (kl,kl+1) and (kl+2,kl+3)
            int mt = row >> 4, r = row & 15;
            int fi = ((r & 7) * 4 + ((kl & 7) >> 1)) * 4
                     + (r >> 3) + ((kl >> 3) << 1);
            uint32_t* base = dA + (mt * 2 + kt) * 128 + fi;
            base[0] = pa[u][0];
            base[4] = pa[u][1];
        }
#pragma unroll
        for (int u = 0; u < 8; u++) {
            int row = l_row[u], c0 = l_c0[u];
            int kt = c0 >> 4, kl = c0 & 15;
            int ntile = row >> 3, nn = row & 7;
            int bi = (nn * 4 + ((kl & 7) >> 1)) * 2 + (kl >> 3);
            uint32_t* base = dB + (ntile * 2 + kt) * 64 + bi;
            base[0] = pb[u][0];
            base[2] = pb[u][1];
        }
    };

    prefetch(0);
    sts_chunk(0);
    __syncthreads();

    for (int c = 0; c < 32; c++) {
        int s = c & 1;
        if (c < 31) prefetch((c + 1) * 32);

        const uint32_t* sA = sh + s * 4096;
        const uint32_t* sB = sA + 2048;
#pragma unroll
        for (int kt = 0; kt < 2; kt++) {
            uint32_t afr[4][4];
            uint32_t bfr[8][2];
#pragma unroll
            for (int mt = 0; mt < 4; mt++)
                *(uint4*)afr[mt] =
                    *(const uint4*)(sA + ((wm * 4 + mt) * 2 + kt) * 128 + lane * 4);
#pragma unroll
            for (int nt = 0; nt < 8; nt++)
                *(uint2*)bfr[nt] =
                    *(const uint2*)(sB + ((wn * 8 + nt) * 2 + kt) * 64 + lane * 2);
#pragma unroll
            for (int mt = 0; mt < 4; mt++)
#pragma unroll
                for (int nt = 0; nt < 8; nt++)
                    mma_f16(d[mt][nt], afr[mt], bfr[nt]);
        }

        if (c < 31) sts_chunk(1 - s);
        __syncthreads();
    }

#pragma unroll
    for (int mt = 0; mt < 4; mt++) {
        int row0 = bm + wm * 64 + mt * 16 + (lane >> 2);
#pragma unroll
        for (int nt = 0; nt < 8; nt++) {
            int col = bn + wn * 64 + nt * 8 + (lane & 3) * 2;
            float bx = bias[col], by = bias[col + 1];
            float2 v0 = make_float2(d[mt][nt][0] + bx, d[mt][nt][1] + by);
            float2 v1 = make_float2(d[mt][nt][2] + bx, d[mt][nt][3] + by);
            if (MODE == 0) {
                *(float2*)&out[(size_t)row0 * EE + col] = v0;
                *(float2*)&out[(size_t)(row0 + 8) * EE + col] = v1;
            } else {
                *(float2*)bhsd_addr(out, row0, col) = v0;
                *(float2*)bhsd_addr(out, row0 + 8, col) = v1;
            }
        }
    }
}

// ---------------------------------------------------------------------------
// RoPE on Q and K in [B,H,S,D] layout.
// ---------------------------------------------------------------------------
__global__ void rope_kernel(float* __restrict__ Q, float* __restrict__ K)
{
    int gid = blockIdx.x * blockDim.x + threadIdx.x;
    int i  = gid & 31;
    int s  = (gid >> 5) & (SS - 1);
    int bh = gid >> 16;
    int base = (bh * SS + s) * DD;

    float freq = exp2f(-(float)i * (13.287712379549449f / 32.0f));
    float ang  = (float)s * freq;
    float sn, cs;
    sincosf(ang, &sn, &cs);

    float q0 = Q[base + i], q1 = Q[base + i + 32];
    Q[base + i]      = q0 * cs - q1 * sn;
    Q[base + i + 32] = q1 * cs + q0 * sn;
    float k0 = K[base + i], k1 = K[base + i + 32];
    K[base + i]      = k0 * cs - k1 * sn;
    K[base + i + 32] = k1 * cs + k0 * sn;
}

// ---------------------------------------------------------------------------
// Flash attention (causal), fp16 mma.sync m16n8k16 (validated round 6).
// ---------------------------------------------------------------------------
#define ATTN_SMEM_BYTES (3 * 2048 * 4)   // 24 KB

__global__ __launch_bounds__(128) void attn_f16(
    const float* __restrict__ Q, const float* __restrict__ K,
    const float* __restrict__ V, float* __restrict__ A)
{
    extern __shared__ uint32_t su[];
    uint32_t* Qs = su;            // 2048
    uint32_t* Ks = su + 2048;
    uint32_t* Vs = su + 4096;

    const int tid  = threadIdx.x;
    const int lane = tid & 31;
    const int w    = tid >> 5;

    const int iq = blockIdx.x;
    const int bh = blockIdx.y;
    const int hb = bh * SS * DD;
    const int q0 = iq * 64;

#pragma unroll
    for (int u = 0; u < 8; u++) {
        int idx = tid + u * 128;
        int row = idx >> 4;
        int c0  = (idx & 15) * 4;
        float4 v = *(const float4*)&Q[hb + (q0 + row) * DD + c0];
        int mt = row >> 4, r = row & 15, kt = c0 >> 4, kl = c0 & 15;
        int fi = ((r & 7) * 4 + ((kl & 7) >> 1)) * 4
                 + (r >> 3) + ((kl >> 3) << 1);
        uint32_t* b = Qs + (mt * 4 + kt) * 128 + fi;
        b[0] = pack_h2(v.x * 0.125f, v.y * 0.125f);
        b[4] = pack_h2(v.z * 0.125f, v.w * 0.125f);
    }

    float o[8][4];
#pragma unroll
    for (int nt = 0; nt < 8; nt++)
#pragma unroll
        for (int e = 0; e < 4; e++) o[nt][e] = 0.f;
    float m0 = -1e30f, m1 = -1e30f, l0 = 0.f, l1 = 0.f;

    for (int j = 0; j <= iq; j++) {
        __syncthreads();

#pragma unroll
        for (int u = 0; u < 8; u++) {
            int idx = tid + u * 128;
            int row = idx >> 4;
            int c0  = (idx & 15) * 4;
            float4 kv4 = *(const float4*)&K[hb + (j * 64 + row) * DD + c0];
            int ntile = row >> 3, nn = row & 7, kt = c0 >> 4, kl = c0 & 15;
            int bi = (nn * 4 + ((kl & 7) >> 1)) * 2 + (kl >> 3);
            uint32_t* b = Ks + (ntile * 4 + kt) * 64 + bi;
            b[0] = pack_h2(kv4.x, kv4.y);
            b[2] = pack_h2(kv4.z, kv4.w);
        }
#pragma unroll
        for (int u = 0; u < 4; u++) {
            int idx = tid + u * 128;
            int pr  = idx >> 4;
            int c0  = (idx & 15) * 4;
            int kv0 = pr * 2;
            float4 a4 = *(const float4*)&V[hb + (j * 64 + kv0) * DD + c0];
            float4 b4 = *(const float4*)&V[hb + (j * 64 + kv0 + 1) * DD + c0];
            int kt = kv0 >> 4, kl = kv0 & 15;
            int hp = (kl & 7) >> 1, reg = kl >> 3;
            int ntile = c0 >> 3, nn = c0 & 7;
            uint32_t* b = Vs + (ntile * 4 + kt) * 64;
            b[(nn + 0) * 8 + hp * 2 + reg] = pack_h2(a4.x, b4.x);
            b[(nn + 1) * 8 + hp * 2 + reg] = pack_h2(a4.y, b4.y);
            b[(nn + 2) * 8 + hp * 2 + reg] = pack_h2(a4.z, b4.z);
            b[(nn + 3) * 8 + hp * 2 + reg] = pack_h2(a4.w, b4.w);
        }
        __syncthreads();

        float s[8][4];
#pragma unroll
        for (int nt = 0; nt < 8; nt++)
#pragma unroll
            for (int e = 0; e < 4; e++) s[nt][e] = 0.f;
#pragma unroll
        for (int kt = 0; kt < 4; kt++) {
            uint32_t af[4];
            *(uint4*)af = *(const uint4*)(Qs + (w * 4 + kt) * 128 + lane * 4);
#pragma unroll
            for (int nt = 0; nt < 8; nt++) {
                uint32_t bf[2];
                *(uint2*)bf = *(const uint2*)(Ks + (nt * 4 + kt) * 64 + lane * 2);
                mma_f16(s[nt], af, bf);
            }
        }

        if (j == iq) {
            int lr = w * 16 + (lane >> 2);
#pragma unroll
            for (int nt = 0; nt < 8; nt++) {
                int lc = nt * 8 + (lane & 3) * 2;
                if (lc > lr)     s[nt][0] = -1e30f;
                if (lc + 1 > lr) s[nt][1] = -1e30f;
                if (lc > lr + 8)     s[nt][2] = -1e30f;
                if (lc + 1 > lr + 8) s[nt][3] = -1e30f;
            }
        }

        float mx0 = m0, mx1 = m1;
#pragma unroll
        for (int nt = 0; nt < 8; nt++) {
            mx0 = fmaxf(mx0, fmaxf(s[nt][0], s[nt][1]));
            mx1 = fmaxf(mx1, fmaxf(s[nt][2], s[nt][3]));
        }
        mx0 = fmaxf(mx0, __shfl_xor_sync(0xffffffffu, mx0, 1));
        mx0 = fmaxf(mx0, __shfl_xor_sync(0xffffffffu, mx0, 2));
        mx1 = fmaxf(mx1, __shfl_xor_sync(0xffffffffu, mx1, 1));
        mx1 = fmaxf(mx1, __shfl_xor_sync(0xffffffffu, mx1, 2));
        float corr0 = __expf(m0 - mx0);
        float corr1 = __expf(m1 - mx1);
        m0 = mx0; m1 = mx1;

        uint32_t ap[4][4];
        float lp0 = 0.f, lp1 = 0.f;
#pragma unroll
        for (int nt = 0; nt < 8; nt++) {
            float p00 = __expf(s[nt][0] - mx0);
            float p01 = __expf(s[nt][1] - mx0);
            float p10 = __expf(s[nt][2] - mx1);
            float p11 = __expf(s[nt][3] - mx1);
            lp0 += p00 + p01;
            lp1 += p10 + p11;
            int kt = nt >> 1, h = (nt & 1) * 2;
            ap[kt][h]     = pack_h2(p00, p01);
            ap[kt][h + 1] = pack_h2(p10, p11);
        }
        lp0 += __shfl_xor_sync(0xffffffffu, lp0, 1);
        lp0 += __shfl_xor_sync(0xffffffffu, lp0, 2);
        lp1 += __shfl_xor_sync(0xffffffffu, lp1, 1);
        lp1 += __shfl_xor_sync(0xffffffffu, lp1, 2);
        l0 = l0 * corr0 + lp0;
        l1 = l1 * corr1 + lp1;

#pragma unroll
        for (int nt = 0; nt < 8; nt++) {
            o[nt][0] *= corr0; o[nt][1] *= corr0;
            o[nt][2] *= corr1; o[nt][3] *= corr1;
        }

#pragma unroll
        for (int kt = 0; kt < 4; kt++) {
#pragma unroll
            for (int nt = 0; nt < 8; nt++) {
                uint32_t bf[2];
                *(uint2*)bf = *(const uint2*)(Vs + (nt * 4 + kt) * 64 + lane * 2);
                mma_f16(o[nt], ap[kt], bf);
            }
        }
    }

    float inv0 = 1.f / l0;
    float inv1 = 1.f / l1;
    int b_ = bh >> 4;
    int h_ = bh & 15;
    int row0 = q0 + w * 16 + (lane >> 2);
#pragma unroll
    for (int nt = 0; nt < 8; nt++) {
        int col = h_ * DD + nt * 8 + (lane & 3) * 2;
        float2 v0 = make_float2(o[nt][0] * inv0, o[nt][1] * inv0);
        float2 v1 = make_float2(o[nt][2] * inv1, o[nt][3] * inv1);
        *(float2*)&A[(size_t)(b_ * SS + row0) * EE + col] = v0;
        *(float2*)&A[(size_t)(b_ * SS + row0 + 8) * EE + col] = v1;
    }
}

// ---------------------------------------------------------------------------
extern "C" void kernel_launch(void* const* d_in, const int* in_sizes, int n_in,
                              void* d_out, int out_size)
{
    const float* x  = (const float*)d_in[0];
    // d_in[1] = mask (causal; structure known statically, unused)
    const float* Wq = (const float*)d_in[2];
    const float* bq = (const float*)d_in[3];
    const float* Wk = (const float*)d_in[4];
    const float* bk = (const float*)d_in[5];
    const float* Wv = (const float*)d_in[6];
    const float* bv = (const float*)d_in[7];
    const float* Wo = (const float*)d_in[8];
    const float* bo = (const float*)d_in[9];

    float *Qp, *Kp, *Vp, *Ap;
    cudaGetSymbolAddress((void**)&Qp, g_Q);
    cudaGetSymbolAddress((void**)&Kp, g_K);
    cudaGetSymbolAddress((void**)&Vp, g_V);
    cudaGetSymbolAddress((void**)&Ap, g_A);

    cudaFuncSetAttribute(gemm_f16v2<0>,
                         cudaFuncAttributeMaxDynamicSharedMemorySize, GEMM_SMEM);
    cudaFuncSetAttribute(gemm_f16v2<1>,
                         cudaFuncAttributeMaxDynamicSharedMemorySize, GEMM_SMEM);
    cudaFuncSetAttribute(attn_f16,
                         cudaFuncAttributeMaxDynamicSharedMemorySize, ATTN_SMEM_BYTES);

    // QKV fused: blockIdx.z selects projection
    gemm_f16v2<1><<<dim3(EE / 128, MM / 128, 3), 128, GEMM_SMEM>>>(
        x, Wq, Wk, Wv, bq, bk, bv, Qp, Kp, Vp);

    rope_kernel<<<(BB * HH * SS * 32) / 256, 256>>>(Qp, Kp);

    attn_f16<<<dim3(SS / 64, BB * HH), 128, ATTN_SMEM_BYTES>>>(Qp, Kp, Vp, Ap);

    // Output projection
    gemm_f16v2<0><<<dim3(EE / 128, MM / 128, 1), 128, GEMM_SMEM>>>(
        Ap, Wo, Wo, Wo, bo, bo, bo, (float*)d_out, (float*)d_out, (float*)d_out);
}